// round 17
// baseline (speedup 1.0000x reference)
#include <cuda_runtime.h>
#include <cuda_fp16.h>
#include <math.h>
#include <stdint.h>

#define N_NODES 50000
#define N_EDGES 800000
#define NEG_SLOPE 0.2f
#define SCAN_NB ((N_NODES + 1023) / 1024)   // 49

// ---------------- scratch (device globals; no allocation allowed) ----------------
__device__ __half g_feath[N_NODES * 256];  // feat converted to fp16
__device__ float  g_ft1[N_NODES * 256];
__device__ __half g_h1h[N_NODES * 256];    // layer-1 output, fp16
__device__ float  g_el1[N_NODES * 4];
__device__ float  g_er1[N_NODES * 4];
__device__ float  g_ft2[N_NODES * 128];
__device__ float  g_el2[N_NODES];
__device__ float  g_er2[N_NODES];
__device__ int    g_cnt[N_NODES];
__device__ int    g_rowptr[N_NODES + 1];
__device__ int    g_bsum[64];
__device__ int    g_colsrc[N_EDGES];
__device__ __half g_wt1h[256 * 256];   // W1^T fp16 [n][k]
__device__ __half g_wt2h[128 * 256];   // W2^T fp16

// ---------------- helpers ----------------
__device__ __forceinline__ uint32_t smem_u32(const void* p) {
    uint32_t a;
    asm("{ .reg .u64 t; cvta.to.shared.u64 t, %1; cvt.u32.u64 %0, t; }" : "=r"(a) : "l"(p));
    return a;
}

#define CP_ASYNC16(sa, gp) \
    asm volatile("cp.async.cg.shared.global [%0], [%1], 16;" :: "r"(sa), "l"(gp) : "memory")
#define CP_ASYNC16_Z(sa, gp, sz) \
    asm volatile("cp.async.cg.shared.global [%0], [%1], 16, %2;" :: "r"(sa), "l"(gp), "r"(sz) : "memory")
#define CP_COMMIT()  asm volatile("cp.async.commit_group;" ::: "memory")
#define CP_WAIT(n)   asm volatile("cp.async.wait_group %0;" :: "n"(n) : "memory")

#define MMA_F16(d, a0, a1, a2, a3, b0, b1)                                    \
    asm volatile("mma.sync.aligned.m16n8k16.row.col.f32.f16.f16.f32 "         \
                 "{%0,%1,%2,%3}, {%4,%5,%6,%7}, {%8,%9}, {%0,%1,%2,%3};"      \
                 : "+f"(d[0]), "+f"(d[1]), "+f"(d[2]), "+f"(d[3])             \
                 : "r"(a0), "r"(a1), "r"(a2), "r"(a3), "r"(b0), "r"(b1))

#define LDSM_X4(r0, r1, r2, r3, addr)                                         \
    asm volatile("ldmatrix.sync.aligned.m8n8.x4.shared.b16 {%0,%1,%2,%3}, [%4];" \
                 : "=r"(r0), "=r"(r1), "=r"(r2), "=r"(r3) : "r"(addr))

// ---------------- small utils ----------------
__global__ void count_dst_kernel(const int* __restrict__ dst, int* __restrict__ cnt, int E) {
    for (int e = blockIdx.x * blockDim.x + threadIdx.x; e < E; e += gridDim.x * blockDim.x)
        atomicAdd(&cnt[dst[e]], 1);
}

// prep: transpose+fp16 W1/W2, convert feat->fp16, zero cnt/el2/er2
__global__ void prep_kernel(const float* __restrict__ feat,
                            const float* __restrict__ W1, const float* __restrict__ W2,
                            __half* __restrict__ feath,
                            __half* __restrict__ t1h, __half* __restrict__ t2h,
                            int* __restrict__ cnt,
                            float* __restrict__ el2, float* __restrict__ er2) {
    int t = blockIdx.x * blockDim.x + threadIdx.x;
    int nt = gridDim.x * blockDim.x;
    if (t < N_NODES) { cnt[t] = 0; el2[t] = 0.f; er2[t] = 0.f; }
    if (t < 65536) {
        int k = t & 255, n = t >> 8;
        t1h[n * 256 + k] = __float2half_rn(W1[k * 256 + n]);
    } else if (t < 98304) {
        int u = t - 65536;
        int k = u & 255, n = u >> 8;
        t2h[n * 256 + k] = __float2half_rn(W2[k * 128 + n]);
    }
    const float2* f2 = (const float2*)feat;
    __half2* fh2 = (__half2*)feath;
    for (int i = t; i < N_NODES * 128; i += nt)
        fh2[i] = __float22half2_rn(f2[i]);
}

// ---- parallel 3-phase scan ----
__global__ __launch_bounds__(1024) void scan1_kernel(const int* __restrict__ cnt,
                                                     int* __restrict__ rowptr,
                                                     int* __restrict__ bsum, int n) {
    __shared__ int warp_sums[32];
    int tid = threadIdx.x, lane = tid & 31, warp = tid >> 5;
    int idx = blockIdx.x * 1024 + tid;
    int v = (idx < n) ? cnt[idx] : 0;
    int x = v;
    #pragma unroll
    for (int off = 1; off < 32; off <<= 1) {
        int y = __shfl_up_sync(0xffffffffu, x, off);
        if (lane >= off) x += y;
    }
    if (lane == 31) warp_sums[warp] = x;
    __syncthreads();
    if (warp == 0) {
        int s = warp_sums[lane];
        #pragma unroll
        for (int off = 1; off < 32; off <<= 1) {
            int y = __shfl_up_sync(0xffffffffu, s, off);
            if (lane >= off) s += y;
        }
        warp_sums[lane] = s;
    }
    __syncthreads();
    int incl = x + ((warp > 0) ? warp_sums[warp - 1] : 0);
    if (idx < n) rowptr[idx + 1] = incl;
    if (tid == 1023) bsum[blockIdx.x] = incl;
}

__global__ void scan2_kernel(int* __restrict__ bsum, int nb) {
    __shared__ int s[64];
    int tid = threadIdx.x;
    s[tid] = (tid < nb) ? bsum[tid] : 0;
    __syncthreads();
    if (tid == 0) {
        int acc = 0;
        for (int i = 0; i < nb; i++) { int t = s[i]; s[i] = acc; acc += t; }
    }
    __syncthreads();
    if (tid < nb) bsum[tid] = s[tid];
}

__global__ void scan3_kernel(int* __restrict__ rowptr, const int* __restrict__ bsum, int n) {
    int idx = blockIdx.x * blockDim.x + threadIdx.x;
    if (idx == 0) rowptr[0] = 0;
    if (idx < n) rowptr[idx + 1] += bsum[idx >> 10];
}

__global__ void scatter_kernel(const int* __restrict__ src, const int* __restrict__ dst,
                               const int* __restrict__ rowptr, int* __restrict__ cnt,
                               int* __restrict__ colsrc, int E) {
    for (int e = blockIdx.x * blockDim.x + threadIdx.x; e < E; e += gridDim.x * blockDim.x) {
        int d = dst[e];
        int pos = atomicSub(&cnt[d], 1);
        colsrc[rowptr[d] + pos - 1] = src[e];
    }
}

// ---------------- pure fp16 MMA GEMM, 3-stage cp.async, 1 barrier/tile ----------------
// HEADS=4: el/er direct store per head=blockIdx.x. HEADS=1: atomicAdd into combined arrays.
template <int HEADS>
__global__ __launch_bounds__(256, 3) void mma_gemm_pf16_kernel(
    const __half* __restrict__ Ath, const __half* __restrict__ Bth,
    float* __restrict__ C,
    const float* __restrict__ attn_l, const float* __restrict__ attn_r,
    float* __restrict__ el, float* __restrict__ er,
    int M, int Nc)
{
    const int BM = 128, BN = 64, BK = 32, K = 256, T = K / BK;
    const int STR2 = 20;            // half2 per row (16 data + 4 pad)
    const int A_STAGE = BM * STR2;  // 2560 half2 = 10240 B
    const int B_STAGE = BN * STR2;  // 1280 half2 = 5120 B
    extern __shared__ float sm[];
    __half2* Ah2 = (__half2*)sm;              // [3][BM][20]
    __half2* Bh2 = Ah2 + 3 * A_STAGE;         // [3][BN][20]

    uint32_t ah_b = smem_u32(Ah2);
    uint32_t bh_b = smem_u32(Bh2);

    int tid = threadIdx.x, lane = tid & 31, warp = tid >> 5;
    int blockRow = blockIdx.y * BM;
    int blockCol = blockIdx.x * BN;
    int g = lane >> 2, q = lane & 3;
    int lm = lane >> 3, lr = lane & 7;
    // A x4: m0=(rows+0,klo) m1=(rows+8,klo) m2=(rows+0,khi) m3=(rows+8,khi)
    uint32_t a_lane_off = (uint32_t)((((lm & 1) * 8 + lr) * 80) + (lm >> 1) * 16);
    // B x4: m0=(j0,klo) m1=(j0,khi) m2=(j1,klo) m3=(j1,khi)
    uint32_t b_lane_off = (uint32_t)((((lm >> 1) * 8 + lr) * 80) + (lm & 1) * 16);

    float acc[8][4];
    #pragma unroll
    for (int j = 0; j < 8; j++)
        #pragma unroll
        for (int c = 0; c < 4; c++) acc[j][c] = 0.f;

    auto load_tile = [&](int t) {
        int buf = t % 3, k0 = t * BK;
        #pragma unroll
        for (int l = 0; l < 2; l++) {
            int c = tid + l * 256;
            int r = c >> 2, ch = c & 3;
            size_t go = (size_t)(blockRow + r) * K + k0 + ch * 8;
            uint32_t so = (uint32_t)((buf * A_STAGE + r * STR2 + ch * 4) * 4);
            uint32_t sz = (blockRow + r < M) ? 16u : 0u;
            CP_ASYNC16_Z(ah_b + so, Ath + go, sz);
        }
        {
            int n = tid >> 2, ch = tid & 3;
            size_t go = (size_t)(blockCol + n) * K + k0 + ch * 8;
            uint32_t so = (uint32_t)((buf * B_STAGE + n * STR2 + ch * 4) * 4);
            CP_ASYNC16(bh_b + so, Bth + go);
        }
        CP_COMMIT();
    };

    load_tile(0);
    load_tile(1);

    #pragma unroll 1
    for (int t = 0; t < T; t++) {
        if (t < T - 1) { CP_WAIT(1); } else { CP_WAIT(0); }
        __syncthreads();
        if (t + 2 < T) load_tile(t + 2);

        int buf = t % 3;
        uint32_t ah_buf = ah_b + (uint32_t)(buf * A_STAGE * 4 + warp * 1280) + a_lane_off;
        uint32_t bh_buf = bh_b + (uint32_t)(buf * B_STAGE * 4) + b_lane_off;

        #pragma unroll
        for (int ks = 0; ks < 2; ks++) {
            uint32_t koff = (uint32_t)(ks * 32);
            uint32_t ah[4];
            LDSM_X4(ah[0], ah[1], ah[2], ah[3], ah_buf + koff);
            #pragma unroll
            for (int p = 0; p < 4; p++) {
                uint32_t bh0, bh1, bh2_, bh3;
                LDSM_X4(bh0, bh1, bh2_, bh3, bh_buf + (uint32_t)(p * 1280) + koff);
                MMA_F16(acc[2 * p],     ah[0], ah[1], ah[2], ah[3], bh0, bh1);
                MMA_F16(acc[2 * p + 1], ah[0], ah[1], ah[2], ah[3], bh2_, bh3);
            }
        }
    }

    // ---- store C (fp32) ----
    int r0 = blockRow + warp * 16 + g;
    int r1 = r0 + 8;
    #pragma unroll
    for (int j = 0; j < 8; j++) {
        int c = blockCol + j * 8 + q * 2;
        if (r0 < M) *(float2*)(C + (size_t)r0 * Nc + c) = make_float2(acc[j][0], acc[j][1]);
        if (r1 < M) *(float2*)(C + (size_t)r1 * Nc + c) = make_float2(acc[j][2], acc[j][3]);
    }

    // ---- fused el/er epilogue ----
    float pl0 = 0.f, pl1 = 0.f, pr0 = 0.f, pr1 = 0.f;
    #pragma unroll
    for (int j = 0; j < 8; j++) {
        int idx = blockCol + j * 8 + q * 2;
        float a0 = __ldg(&attn_l[idx]), a1 = __ldg(&attn_l[idx + 1]);
        float b0 = __ldg(&attn_r[idx]), b1 = __ldg(&attn_r[idx + 1]);
        pl0 += acc[j][0] * a0 + acc[j][1] * a1;
        pl1 += acc[j][2] * a0 + acc[j][3] * a1;
        pr0 += acc[j][0] * b0 + acc[j][1] * b1;
        pr1 += acc[j][2] * b0 + acc[j][3] * b1;
    }
    #pragma unroll
    for (int off = 1; off <= 2; off <<= 1) {
        pl0 += __shfl_xor_sync(0xffffffffu, pl0, off);
        pl1 += __shfl_xor_sync(0xffffffffu, pl1, off);
        pr0 += __shfl_xor_sync(0xffffffffu, pr0, off);
        pr1 += __shfl_xor_sync(0xffffffffu, pr1, off);
    }
    if (q == 0) {
        if (HEADS == 4) {
            if (r0 < M) {
                el[(size_t)r0 * 4 + blockIdx.x] = pl0;
                er[(size_t)r0 * 4 + blockIdx.x] = pr0;
            }
            if (r1 < M) {
                el[(size_t)r1 * 4 + blockIdx.x] = pl1;
                er[(size_t)r1 * 4 + blockIdx.x] = pr1;
            }
        } else {
            if (r0 < M) { atomicAdd(&el[r0], pl0); atomicAdd(&er[r0], pr0); }
            if (r1 < M) { atomicAdd(&el[r1], pl1); atomicAdd(&er[r1], pr1); }
        }
    }
}

// ---------------- fused softmax + aggregation ----------------
__device__ __forceinline__ float leaky_exp(float e) {
    e = (e > 0.f) ? e : NEG_SLOPE * e;
    return __expf(e);
}

// layer 1: H=4, D=64, C=256, fp32 features. One warp per node. Output h1 as fp16.
__global__ __launch_bounds__(256) void aggregate1_kernel(
    const float* __restrict__ ft, const float* __restrict__ el, const float* __restrict__ er,
    const int* __restrict__ rowptr, const int* __restrict__ colsrc,
    const float* __restrict__ bias, __half* __restrict__ outh, int Nn)
{
    int warp = threadIdx.x >> 5, lane = threadIdx.x & 31;
    int n = blockIdx.x * 8 + warp;
    if (n >= Nn) return;
    int start = rowptr[n];
    int deg = rowptr[n + 1] - start;

    const bool hlo = (lane < 16);
    float4 er4 = __ldg((const float4*)(er + (size_t)n * 4));
    float erA = hlo ? er4.x : er4.y;
    float erB = hlo ? er4.z : er4.w;

    float4 accA = make_float4(0.f, 0.f, 0.f, 0.f);
    float4 accB = make_float4(0.f, 0.f, 0.f, 0.f);
    float wsumA = 0.f, wsumB = 0.f;
    const float* ftA = ft + lane * 4;
    const float* ftB = ft + 128 + lane * 4;

    int k = 0;
    for (; k + 4 <= deg; k += 4) {
        int s0 = __ldg(&colsrc[start + k + 0]);
        int s1 = __ldg(&colsrc[start + k + 1]);
        int s2 = __ldg(&colsrc[start + k + 2]);
        int s3 = __ldg(&colsrc[start + k + 3]);
        float4 l0 = __ldg((const float4*)(el + (size_t)s0 * 4));
        float4 l1 = __ldg((const float4*)(el + (size_t)s1 * 4));
        float4 l2 = __ldg((const float4*)(el + (size_t)s2 * 4));
        float4 l3 = __ldg((const float4*)(el + (size_t)s3 * 4));
        float4 fA0 = *(const float4*)(ftA + (size_t)s0 * 256);
        float4 fB0 = *(const float4*)(ftB + (size_t)s0 * 256);
        float4 fA1 = *(const float4*)(ftA + (size_t)s1 * 256);
        float4 fB1 = *(const float4*)(ftB + (size_t)s1 * 256);
        float4 fA2 = *(const float4*)(ftA + (size_t)s2 * 256);
        float4 fB2 = *(const float4*)(ftB + (size_t)s2 * 256);
        float4 fA3 = *(const float4*)(ftA + (size_t)s3 * 256);
        float4 fB3 = *(const float4*)(ftB + (size_t)s3 * 256);
        float wA0 = leaky_exp((hlo ? l0.x : l0.y) + erA);
        float wB0 = leaky_exp((hlo ? l0.z : l0.w) + erB);
        float wA1 = leaky_exp((hlo ? l1.x : l1.y) + erA);
        float wB1 = leaky_exp((hlo ? l1.z : l1.w) + erB);
        float wA2 = leaky_exp((hlo ? l2.x : l2.y) + erA);
        float wB2 = leaky_exp((hlo ? l2.z : l2.w) + erB);
        float wA3 = leaky_exp((hlo ? l3.x : l3.y) + erA);
        float wB3 = leaky_exp((hlo ? l3.z : l3.w) + erB);
        accA.x += wA0 * fA0.x + wA1 * fA1.x + wA2 * fA2.x + wA3 * fA3.x;
        accA.y += wA0 * fA0.y + wA1 * fA1.y + wA2 * fA2.y + wA3 * fA3.y;
        accA.z += wA0 * fA0.z + wA1 * fA1.z + wA2 * fA2.z + wA3 * fA3.z;
        accA.w += wA0 * fA0.w + wA1 * fA1.w + wA2 * fA2.w + wA3 * fA3.w;
        accB.x += wB0 * fB0.x + wB1 * fB1.x + wB2 * fB2.x + wB3 * fB3.x;
        accB.y += wB0 * fB0.y + wB1 * fB1.y + wB2 * fB2.y + wB3 * fB3.y;
        accB.z += wB0 * fB0.z + wB1 * fB1.z + wB2 * fB2.z + wB3 * fB3.z;
        accB.w += wB0 * fB0.w + wB1 * fB1.w + wB2 * fB2.w + wB3 * fB3.w;
        wsumA += (wA0 + wA1) + (wA2 + wA3);
        wsumB += (wB0 + wB1) + (wB2 + wB3);
    }
    for (; k < deg; k++) {
        int s0 = __ldg(&colsrc[start + k]);
        float4 l0 = __ldg((const float4*)(el + (size_t)s0 * 4));
        float4 fA0 = *(const float4*)(ftA + (size_t)s0 * 256);
        float4 fB0 = *(const float4*)(ftB + (size_t)s0 * 256);
        float wA0 = leaky_exp((hlo ? l0.x : l0.y) + erA);
        float wB0 = leaky_exp((hlo ? l0.z : l0.w) + erB);
        accA.x += wA0 * fA0.x; accA.y += wA0 * fA0.y;
        accA.z += wA0 * fA0.z; accA.w += wA0 * fA0.w;
        accB.x += wB0 * fB0.x; accB.y += wB0 * fB0.y;
        accB.z += wB0 * fB0.z; accB.w += wB0 * fB0.w;
        wsumA += wA0; wsumB += wB0;
    }

    float invA = (deg > 0) ? (1.f / wsumA) : 0.f;
    float invB = (deg > 0) ? (1.f / wsumB) : 0.f;
    float4 bA = __ldg((const float4*)(bias + lane * 4));
    float4 bB = __ldg((const float4*)(bias + 128 + lane * 4));
    float4 oA, oB;
    oA.x = fmaxf(accA.x * invA + bA.x, 0.f);
    oA.y = fmaxf(accA.y * invA + bA.y, 0.f);
    oA.z = fmaxf(accA.z * invA + bA.z, 0.f);
    oA.w = fmaxf(accA.w * invA + bA.w, 0.f);
    oB.x = fmaxf(accB.x * invB + bB.x, 0.f);
    oB.y = fmaxf(accB.y * invB + bB.y, 0.f);
    oB.z = fmaxf(accB.z * invB + bB.z, 0.f);
    oB.w = fmaxf(accB.w * invB + bB.w, 0.f);

    __half2 hA0 = __floats2half2_rn(oA.x, oA.y);
    __half2 hA1 = __floats2half2_rn(oA.z, oA.w);
    __half2 hB0 = __floats2half2_rn(oB.x, oB.y);
    __half2 hB1 = __floats2half2_rn(oB.z, oB.w);
    *(uint2*)(outh + (size_t)n * 256 + lane * 4) =
        make_uint2(*(uint32_t*)&hA0, *(uint32_t*)&hA1);
    *(uint2*)(outh + (size_t)n * 256 + 128 + lane * 4) =
        make_uint2(*(uint32_t*)&hB0, *(uint32_t*)&hB1);
}

// layer 2: H=1, D=128, fp32 features. Combined el/er arrays.
__global__ __launch_bounds__(256) void aggregate2_kernel(
    const float* __restrict__ ft, const float* __restrict__ el, const float* __restrict__ er,
    const int* __restrict__ rowptr, const int* __restrict__ colsrc,
    const float* __restrict__ bias, float* __restrict__ out, int Nn)
{
    int warp = threadIdx.x >> 5, lane = threadIdx.x & 31;
    int n = blockIdx.x * 8 + warp;
    if (n >= Nn) return;
    int start = rowptr[n];
    int deg = rowptr[n + 1] - start;

    float er_n = __ldg(&er[n]);
    float4 acc = make_float4(0.f, 0.f, 0.f, 0.f);
    float wsum = 0.f;
    const float* ftp = ft + lane * 4;

    int k = 0;
    for (; k + 8 <= deg; k += 8) {
        int s[8];
        #pragma unroll
        for (int u = 0; u < 8; u++) s[u] = __ldg(&colsrc[start + k + u]);
        float e[8];
        #pragma unroll
        for (int u = 0; u < 8; u++) e[u] = __ldg(&el[s[u]]);
        float4 f[8];
        #pragma unroll
        for (int u = 0; u < 8; u++) f[u] = *(const float4*)(ftp + (size_t)s[u] * 128);
        #pragma unroll
        for (int u = 0; u < 8; u++) {
            float w = leaky_exp(e[u] + er_n);
            acc.x += w * f[u].x; acc.y += w * f[u].y;
            acc.z += w * f[u].z; acc.w += w * f[u].w;
            wsum += w;
        }
    }
    for (; k < deg; k++) {
        int s0 = __ldg(&colsrc[start + k]);
        float w = leaky_exp(__ldg(&el[s0]) + er_n);
        float4 f0 = *(const float4*)(ftp + (size_t)s0 * 128);
        acc.x += w * f0.x; acc.y += w * f0.y;
        acc.z += w * f0.z; acc.w += w * f0.w;
        wsum += w;
    }

    float inv = (deg > 0) ? (1.f / wsum) : 0.f;
    float4 b = __ldg((const float4*)(bias + lane * 4));
    float4 o;
    o.x = acc.x * inv + b.x;
    o.y = acc.y * inv + b.y;
    o.z = acc.z * inv + b.z;
    o.w = acc.w * inv + b.w;
    *(float4*)(out + (size_t)n * 128 + lane * 4) = o;
}

// ---------------- launch (single stream) ----------------
extern "C" void kernel_launch(void* const* d_in, const int* in_sizes, int n_in,
                              void* d_out, int out_size)
{
    const float* feat    = (const float*)d_in[0];
    const int*   src     = (const int*)  d_in[1];
    const int*   dst     = (const int*)  d_in[2];
    const float* W1      = (const float*)d_in[3];
    const float* attn_l1 = (const float*)d_in[4];
    const float* attn_r1 = (const float*)d_in[5];
    const float* bias1   = (const float*)d_in[6];
    const float* W2      = (const float*)d_in[7];
    const float* attn_l2 = (const float*)d_in[8];
    const float* attn_r2 = (const float*)d_in[9];
    const float* bias2   = (const float*)d_in[10];
    float* out = (float*)d_out;

    float *ft1, *el1, *er1, *ft2, *el2, *er2;
    __half *feath, *h1h, *wt1h, *wt2h;
    int *cnt, *rowptr, *colsrc, *bsum;
    cudaGetSymbolAddress((void**)&feath,  g_feath);
    cudaGetSymbolAddress((void**)&ft1,    g_ft1);
    cudaGetSymbolAddress((void**)&h1h,    g_h1h);
    cudaGetSymbolAddress((void**)&el1,    g_el1);
    cudaGetSymbolAddress((void**)&er1,    g_er1);
    cudaGetSymbolAddress((void**)&ft2,    g_ft2);
    cudaGetSymbolAddress((void**)&el2,    g_el2);
    cudaGetSymbolAddress((void**)&er2,    g_er2);
    cudaGetSymbolAddress((void**)&wt1h,   g_wt1h);
    cudaGetSymbolAddress((void**)&wt2h,   g_wt2h);
    cudaGetSymbolAddress((void**)&cnt,    g_cnt);
    cudaGetSymbolAddress((void**)&rowptr, g_rowptr);
    cudaGetSymbolAddress((void**)&colsrc, g_colsrc);
    cudaGetSymbolAddress((void**)&bsum,   g_bsum);

    const int SMEM_SZ = (3 * 128 * 20 + 3 * 64 * 20) * 4;   // 46080
    cudaFuncSetAttribute(mma_gemm_pf16_kernel<4>, cudaFuncAttributeMaxDynamicSharedMemorySize, SMEM_SZ);
    cudaFuncSetAttribute(mma_gemm_pf16_kernel<1>, cudaFuncAttributeMaxDynamicSharedMemorySize, SMEM_SZ);

    prep_kernel<<<2048, 256>>>(feat, W1, W2, feath, wt1h, wt2h, cnt, el2, er2);    // 1
    count_dst_kernel<<<2048, 256>>>(dst, cnt, N_EDGES);                            // 2
    scan1_kernel<<<SCAN_NB, 1024>>>(cnt, rowptr, bsum, N_NODES);                   // 3
    {                                                                              // 4: gemm1 (profiled)
        dim3 grid(4, (N_NODES + 127) / 128);
        mma_gemm_pf16_kernel<4><<<grid, 256, SMEM_SZ>>>(feath, wt1h, ft1,
                                                        attn_l1, attn_r1, el1, er1,
                                                        N_NODES, 256);
    }
    scan2_kernel<<<1, 64>>>(bsum, SCAN_NB);                                        // 5
    scan3_kernel<<<(N_NODES + 255) / 256, 256>>>(rowptr, bsum, N_NODES);           // 6
    scatter_kernel<<<2048, 256>>>(src, dst, rowptr, cnt, colsrc, N_EDGES);         // 7
    aggregate1_kernel<<<(N_NODES + 7) / 8, 256>>>(ft1, el1, er1, rowptr, colsrc,   // 8
                                                  bias1, h1h, N_NODES);
    {                                                                              // 9: gemm2
        dim3 grid(2, (N_NODES + 127) / 128);
        mma_gemm_pf16_kernel<1><<<grid, 256, SMEM_SZ>>>(h1h, wt2h, ft2,
                                                        attn_l2, attn_r2, el2, er2,
                                                        N_NODES, 128);
    }
    aggregate2_kernel<<<(N_NODES + 7) / 8, 256>>>(ft2, el2, er2, rowptr, colsrc,   // 10
                                                  bias2, out, N_NODES);
}